// round 3
// baseline (speedup 1.0000x reference)
#include <cuda_runtime.h>

// 128 batches per block, 1 thread per batch; each WARP stages its own tile.
constexpr int BPB = 128;              // threads per block
constexpr int WARPS = BPB / 32;       // 4
constexpr int FLOATS_PER_BATCH = 63;  // 21 joints * 3
constexpr int WARP_FLOATS = 32 * FLOATS_PER_BATCH;  // 2016 floats per warp tile
constexpr int NBLOCKS = 4096;         // 524288 / 128
constexpr int NPARTIALS = NBLOCKS * WARPS;  // 16384 per-warp partials

// Scratch: per-warp partial sums (deterministic two-pass reduction; no allocs).
__device__ float g_partials[NPARTIALS];

__global__ __launch_bounds__(BPB) void joint_angle_loss_kernel(const float* __restrict__ gt) {
    __shared__ float s[WARPS * WARP_FLOATS];  // 32256 B

    const int warp = threadIdx.x >> 5;
    const int lane = threadIdx.x & 31;

    // This warp's 32 batches start here in GMEM (contiguous 8064 B chunk).
    const long long warp_base =
        ((long long)blockIdx.x * WARPS + warp) * WARP_FLOATS;
    const float4* __restrict__ src = reinterpret_cast<const float4*>(gt + warp_base);
    float4* dst = reinterpret_cast<float4*>(s + warp * WARP_FLOATS);

    // 2016/4 = 504 float4 per warp; ~16 per lane, coalesced 512B/iteration.
    constexpr int N4 = WARP_FLOATS / 4;
    #pragma unroll
    for (int i = lane; i < N4; i += 32) {
        dst[i] = src[i];
    }
    __syncwarp();

    // Row stride 63 floats: odd stride -> conflict-free LDS across the warp.
    const float* __restrict__ p = s + warp * WARP_FLOATS + lane * FLOATS_PER_BATCH;

    float total = 0.0f;

    #pragma unroll
    for (int f = 0; f < 5; f++) {
        // Finger f uses joints 4f .. 4f+4 -> floats at offset 12f .. 12f+14
        const float* q = p + 12 * f;

        const float p0x = q[0],  p0y = q[1],  p0z = q[2];
        const float p1x = q[3],  p1y = q[4],  p1z = q[5];
        const float p2x = q[6],  p2y = q[7],  p2z = q[8];
        const float p3x = q[9],  p3y = q[10], p3z = q[11];
        const float p4x = q[12], p4y = q[13], p4z = q[14];

        const float b1x = p1x - p0x, b1y = p1y - p0y, b1z = p1z - p0z;
        const float b2x = p2x - p1x, b2y = p2y - p1y, b2z = p2z - p1z;
        const float b3x = p3x - p2x, b3y = p3y - p2y, b3z = p3z - p2z;
        const float b4x = p4x - p3x, b4y = p4y - p3y, b4z = p4z - p3z;

        // r_tip = cross(b4, b3)
        const float rtx = b4y * b3z - b4z * b3y;
        const float rty = b4z * b3x - b4x * b3z;
        const float rtz = b4x * b3y - b4y * b3x;
        // r_mid = cross(b3, b2)
        const float rmx = b3y * b2z - b3z * b2y;
        const float rmy = b3z * b2x - b3x * b2z;
        const float rmz = b3x * b2y - b3y * b2x;
        // r_palm = cross(b2, b1)
        const float rpx = b2y * b1z - b2z * b1y;
        const float rpy = b2z * b1x - b2x * b1z;
        const float rpz = b2x * b1y - b2y * b1x;

        // main = dot(r_palm, b4) + dot(r_mid, b4)
        const float main_v = (rpx + rmx) * b4x + (rpy + rmy) * b4y + (rpz + rmz) * b4z;

        const float d1 = rtx * rmx + rty * rmy + rtz * rmz;
        const float d2 = rpx * rmx + rpy * rmy + rpz * rmz;

        float pen = 0.0f;
        if (d1 < 0.0f) pen += d1 * d1;
        if (d2 < 0.0f) pen += d2 * d2;

        total += main_v + pen;
    }

    // Warp tree reduce (fixed order -> deterministic)
    #pragma unroll
    for (int off = 16; off > 0; off >>= 1)
        total += __shfl_xor_sync(0xFFFFFFFFu, total, off);

    if (lane == 0)
        g_partials[blockIdx.x * WARPS + warp] = total;
}

// One block reduces the 16384 partials in a fixed order (deterministic).
__global__ __launch_bounds__(1024) void finalize_kernel(float* __restrict__ out) {
    const int tid = threadIdx.x;

    // Each thread sums 16 partials sequentially in double (fixed order).
    double acc = 0.0;
    #pragma unroll
    for (int k = 0; k < NPARTIALS / 1024; k++)
        acc += (double)g_partials[tid + k * 1024];

    // Warp tree reduce on doubles (fixed order).
    #pragma unroll
    for (int off = 16; off > 0; off >>= 1)
        acc += __shfl_xor_sync(0xFFFFFFFFu, acc, off);

    __shared__ double wsum[32];
    if ((tid & 31) == 0) wsum[tid >> 5] = acc;
    __syncthreads();

    if (tid == 0) {
        double t = 0.0;
        #pragma unroll
        for (int w = 0; w < 32; w++) t += wsum[w];
        out[0] = (float)t;
    }
}

extern "C" void kernel_launch(void* const* d_in, const int* in_sizes, int n_in,
                              void* d_out, int out_size) {
    // d_in[0] = pose23d_pred (unused by the reference computation)
    // d_in[1] = pose23d_gt   (B, 21, 3) float32
    const float* gt = (const float*)d_in[1];
    float* out = (float*)d_out;

    joint_angle_loss_kernel<<<NBLOCKS, BPB>>>(gt);
    finalize_kernel<<<1, 1024>>>(out);
}

// round 6
// speedup vs baseline: 1.3174x; 1.3174x over previous
#include <cuda_runtime.h>

// 128 batches per block, 1 thread per batch; each WARP stages its own tile.
constexpr int BPB = 128;              // threads per block
constexpr int WARPS = BPB / 32;       // 4
constexpr int FLOATS_PER_BATCH = 63;  // 21 joints * 3
constexpr int WARP_FLOATS = 32 * FLOATS_PER_BATCH;  // 2016 floats per warp tile
constexpr int NBLOCKS = 4096;         // 524288 / 128

// Scratch (device globals; no allocations).
__device__ float g_partials[NBLOCKS];
__device__ unsigned int g_count = 0;  // self-resetting across graph replays

__global__ __launch_bounds__(BPB) void joint_angle_loss_kernel(
    const float* __restrict__ gt, float* __restrict__ out) {
    __shared__ float s[WARPS * WARP_FLOATS];  // 32256 B
    __shared__ float wsum[WARPS];
    __shared__ bool s_is_last;

    const int warp = threadIdx.x >> 5;
    const int lane = threadIdx.x & 31;

    // This warp's 32 batches start here in GMEM (contiguous 8064 B chunk).
    const long long warp_base =
        ((long long)blockIdx.x * WARPS + warp) * WARP_FLOATS;
    const float4* __restrict__ src = reinterpret_cast<const float4*>(gt + warp_base);
    float4* dst = reinterpret_cast<float4*>(s + warp * WARP_FLOATS);

    // 2016/4 = 504 float4 per warp; ~16 per lane in flight, coalesced.
    constexpr int N4 = WARP_FLOATS / 4;
    #pragma unroll
    for (int i = lane; i < N4; i += 32) {
        dst[i] = src[i];
    }
    __syncwarp();

    // Row stride 63 floats: odd stride -> conflict-free LDS across the warp.
    const float* __restrict__ p = s + warp * WARP_FLOATS + lane * FLOATS_PER_BATCH;

    float total = 0.0f;

    #pragma unroll
    for (int f = 0; f < 5; f++) {
        const float* q = p + 12 * f;

        const float p0x = q[0],  p0y = q[1],  p0z = q[2];
        const float p1x = q[3],  p1y = q[4],  p1z = q[5];
        const float p2x = q[6],  p2y = q[7],  p2z = q[8];
        const float p3x = q[9],  p3y = q[10], p3z = q[11];
        const float p4x = q[12], p4y = q[13], p4z = q[14];

        const float b1x = p1x - p0x, b1y = p1y - p0y, b1z = p1z - p0z;
        const float b2x = p2x - p1x, b2y = p2y - p1y, b2z = p2z - p1z;
        const float b3x = p3x - p2x, b3y = p3y - p2y, b3z = p3z - p2z;
        const float b4x = p4x - p3x, b4y = p4y - p3y, b4z = p4z - p3z;

        // r_tip = cross(b4, b3)
        const float rtx = b4y * b3z - b4z * b3y;
        const float rty = b4z * b3x - b4x * b3z;
        const float rtz = b4x * b3y - b4y * b3x;
        // r_mid = cross(b3, b2)
        const float rmx = b3y * b2z - b3z * b2y;
        const float rmy = b3z * b2x - b3x * b2z;
        const float rmz = b3x * b2y - b3y * b2x;
        // r_palm = cross(b2, b1)
        const float rpx = b2y * b1z - b2z * b1y;
        const float rpy = b2z * b1x - b2x * b1z;
        const float rpz = b2x * b1y - b2y * b1x;

        // main = dot(r_palm, b4) + dot(r_mid, b4)
        const float main_v = (rpx + rmx) * b4x + (rpy + rmy) * b4y + (rpz + rmz) * b4z;

        const float d1 = rtx * rmx + rty * rmy + rtz * rmz;
        const float d2 = rpx * rmx + rpy * rmy + rpz * rmz;

        float pen = 0.0f;
        if (d1 < 0.0f) pen += d1 * d1;
        if (d2 < 0.0f) pen += d2 * d2;

        total += main_v + pen;
    }

    // Warp tree reduce (fixed order -> deterministic)
    #pragma unroll
    for (int off = 16; off > 0; off >>= 1)
        total += __shfl_xor_sync(0xFFFFFFFFu, total, off);

    if (lane == 0) wsum[warp] = total;
    __syncthreads();

    if (threadIdx.x == 0) {
        float bs = 0.0f;
        #pragma unroll
        for (int w = 0; w < WARPS; w++) bs += wsum[w];
        g_partials[blockIdx.x] = bs;
        __threadfence();
        unsigned int done = atomicAdd(&g_count, 1u);
        s_is_last = (done == (unsigned)(NBLOCKS - 1));
    }
    __syncthreads();

    // Last-arriving block performs the final reduction in a FIXED order
    // (deterministic: atomics only select the reducer, never the arithmetic).
    if (s_is_last) {
        __threadfence();  // make all g_partials writes visible

        // 128 threads x 8 float4 = 4096 partials, L2-hot, coalesced LDG.128.
        const float4* __restrict__ part4 = reinterpret_cast<const float4*>(g_partials);
        double acc = 0.0;
        #pragma unroll
        for (int k = 0; k < NBLOCKS / (BPB * 4); k++) {
            float4 v = part4[threadIdx.x + k * BPB];
            acc += (double)v.x + (double)v.y + (double)v.z + (double)v.w;
        }

        #pragma unroll
        for (int off = 16; off > 0; off >>= 1)
            acc += __shfl_xor_sync(0xFFFFFFFFu, acc, off);

        __shared__ double dsum[WARPS];
        if (lane == 0) dsum[warp] = acc;
        __syncthreads();

        if (threadIdx.x == 0) {
            double t = 0.0;
            #pragma unroll
            for (int w = 0; w < WARPS; w++) t += dsum[w];
            out[0] = (float)t;
            g_count = 0;  // reset for next graph replay (all blocks have arrived)
        }
    }
}

extern "C" void kernel_launch(void* const* d_in, const int* in_sizes, int n_in,
                              void* d_out, int out_size) {
    // d_in[0] = pose23d_pred (unused by the reference computation)
    // d_in[1] = pose23d_gt   (B, 21, 3) float32
    const float* gt = (const float*)d_in[1];
    float* out = (float*)d_out;

    joint_angle_loss_kernel<<<NBLOCKS, BPB>>>(gt, out);
}